// round 7
// baseline (speedup 1.0000x reference)
#include <cuda_runtime.h>
#include <cuda_bf16.h>
#include <cstdint>

#define BB 2
#define TT 4
#define CK 64
#define CV 256
#define HH 64
#define WW 64
#define PH 32
#define PW 32
#define MM 4096
#define NN 4096
#define SCALE 0.125f

// Scratch (device globals: allocation-free)
__device__ __align__(128) __nv_bfloat16 g_qk[(size_t)BB * CK * NN];   // scaled Q, bf16 [b][ck][n]
__device__ __align__(128) __nv_bfloat16 g_mk[(size_t)BB * MM * CK];   // pooled K, bf16 [b][m][ck]
__device__ __align__(128) __nv_bfloat16 g_mv[(size_t)BB * CV * MM];   // pooled V, bf16 [b][c][m]

__device__ __forceinline__ void cpasync16(uint32_t saddr, const void* g) {
    asm volatile("cp.async.cg.shared.global [%0], [%1], 16;" :: "r"(saddr), "l"(g));
}
__device__ __forceinline__ void ldsm4(uint32_t* r, uint32_t a) {
    asm volatile("ldmatrix.sync.aligned.m8n8.x4.shared.b16 {%0,%1,%2,%3},[%4];"
                 : "=r"(r[0]), "=r"(r[1]), "=r"(r[2]), "=r"(r[3]) : "r"(a));
}
__device__ __forceinline__ void ldsm4t(uint32_t* r, uint32_t a) {
    asm volatile("ldmatrix.sync.aligned.m8n8.x4.trans.shared.b16 {%0,%1,%2,%3},[%4];"
                 : "=r"(r[0]), "=r"(r[1]), "=r"(r[2]), "=r"(r[3]) : "r"(a));
}
__device__ __forceinline__ void mma_bf16(float* d, const uint32_t* a, const uint32_t* b) {
    asm volatile(
        "mma.sync.aligned.m16n8k16.row.col.f32.bf16.bf16.f32 "
        "{%0,%1,%2,%3},{%4,%5,%6,%7},{%8,%9},{%0,%1,%2,%3};"
        : "+f"(d[0]), "+f"(d[1]), "+f"(d[2]), "+f"(d[3])
        : "r"(a[0]), "r"(a[1]), "r"(a[2]), "r"(a[3]), "r"(b[0]), "r"(b[1]));
}
__device__ __forceinline__ uint32_t pack_bf16x2(float a, float b) {
    __nv_bfloat162 h = __floats2bfloat162_rn(a, b);
    return *reinterpret_cast<uint32_t*>(&h);
}

// ---------------- fused prep: cvtq + pool_keys + pool_vals in one launch ----------------
// blocks [0,512): cvtq; [512,2560): pool_k; [2560,10752): pool_v
__global__ void __launch_bounds__(256) prep_kernel(const float* __restrict__ mk_in,
                                                   const float* __restrict__ mv_in,
                                                   const float* __restrict__ q_in) {
    int blk = blockIdx.x;
    if (blk < 512) {
        int i = blk * 256 + threadIdx.x;                 // float4 index
        float4 v = ((const float4*)q_in)[i];
        __nv_bfloat162* dst = (__nv_bfloat162*)g_qk;
        dst[2 * i]     = __floats2bfloat162_rn(v.x * SCALE, v.y * SCALE);
        dst[2 * i + 1] = __floats2bfloat162_rn(v.z * SCALE, v.w * SCALE);
    } else if (blk < 2560) {
        int idx = (blk - 512) * 256 + threadIdx.x;
        int pw = idx & 31; int t1 = idx >> 5;
        int ph = t1 & 31;  int t2 = t1 >> 5;
        int ck = t2 & 63;  int t3 = t2 >> 6;
        int t  = t3 & 3;   int b  = t3 >> 2;
        const float* base = mk_in + ((((size_t)(b * TT + t) * CK + ck) * HH + ph * 2) * WW + pw * 2);
        float v = fmaxf(fmaxf(base[0], base[1]), fmaxf(base[WW], base[WW + 1]));
        int m = t * (PH * PW) + ph * PW + pw;
        g_mk[((size_t)b * MM + m) * CK + ck] = __float2bfloat16_rn(v);
    } else {
        int idx = (blk - 2560) * 256 + threadIdx.x;
        int pw = idx & 31; int t1 = idx >> 5;
        int ph = t1 & 31;  int t2 = t1 >> 5;
        int c  = t2 & 255; int t3 = t2 >> 8;
        int t  = t3 & 3;   int b  = t3 >> 2;
        const float* base = mv_in + ((((size_t)(b * TT + t) * CV + c) * HH + ph * 2) * WW + pw * 2);
        float v = fmaxf(fmaxf(base[0], base[1]), fmaxf(base[WW], base[WW + 1]));
        int m = t * (PH * PW) + ph * PW + pw;
        g_mv[((size_t)b * CV + c) * MM + m] = __float2bfloat16_rn(v);
    }
}

// ---------------- fused attention, register-fragment P, 8 warps/CTA ----------------
// CTA: 64n x 128c, 8 warps = 4 n-slices (16n) x 2 c-halves (64c). S duplicated per c-half.
// grid (2 c, 64 n, 2 b) = 256 CTAs, 2 CTAs/SM -> ~14 warps/SM.
// smem: Qs[64ck][72n] @0 (9216B) | 3 stages: Ks[64m][72ck] (9216) + Vs[128c][72m] (18432)
#define QS_B 9216u
#define STG_B 27648u
#define SMEM_TOTAL (QS_B + 3u * STG_B)   // 92160

__global__ void __launch_bounds__(256, 2) fused_attn_kernel(float* __restrict__ out) {
    extern __shared__ char sm[];
    const uint32_t sb = (uint32_t)__cvta_generic_to_shared(sm);
    const int b = blockIdx.z, n0 = blockIdx.y * 64, c0 = blockIdx.x * 128;
    const int tid = threadIdx.x;

    const __nv_bfloat16* qb = g_qk + (size_t)b * CK * NN;
    const __nv_bfloat16* kb = g_mk + (size_t)b * MM * CK;
    const __nv_bfloat16* vb = g_mv + (size_t)b * CV * MM;

    // Q load: 64 ck-rows x 8 segs of 16B (row pitch 144B) = 512 ops
    #pragma unroll
    for (int i = 0; i < 2; i++) {
        int e = tid + i * 256;
        int row = e >> 3, seg = e & 7;
        cpasync16(sb + (uint32_t)(row * 144 + seg * 16),
                  qb + (size_t)row * NN + n0 + seg * 8);
    }
    asm volatile("cp.async.commit_group;" ::: "memory");

    auto pf = [&](int ch) {
        uint32_t kst = sb + QS_B + (uint32_t)(ch % 3) * STG_B;
        uint32_t vst = kst + 9216u;
        #pragma unroll
        for (int i = 0; i < 2; i++) {          // K: 64 m-rows x 8 segs
            int e = tid + i * 256;
            int row = e >> 3, seg = e & 7;
            cpasync16(kst + (uint32_t)(row * 144 + seg * 16),
                      kb + (size_t)(ch * 64 + row) * CK + seg * 8);
        }
        #pragma unroll
        for (int i = 0; i < 4; i++) {          // V: 128 c-rows x 8 segs
            int e = tid + i * 256;
            int row = e >> 3, seg = e & 7;
            cpasync16(vst + (uint32_t)(row * 144 + seg * 16),
                      vb + (size_t)(c0 + row) * MM + ch * 64 + seg * 8);
        }
        asm volatile("cp.async.commit_group;" ::: "memory");
    };
    pf(0); pf(1);

    const int wid = tid >> 5, lane = tid & 31;
    const int wn = (wid & 3) * 16;             // warp n base (local)
    const int wc = (wid >> 2) * 64;            // warp c base (local)
    const int g = lane >> 2, t = lane & 3;
    const int lr = (lane & 7) + ((lane >> 4) << 3);
    const int lh = (lane >> 3) & 1;

    // wait for Q, then preload Q A-fragments (16n x 64k -> 4 frags)
    asm volatile("cp.async.wait_group 2;" ::: "memory");
    __syncthreads();
    uint32_t q[4][4];
    #pragma unroll
    for (int kf = 0; kf < 4; kf++)
        ldsm4t(q[kf], sb + (uint32_t)((kf * 16 + lr) * 144 + (wn + lh * 8) * 2));

    float acc_o[8][4] = {};
    float rs0 = 0.f, rs1 = 0.f;

    const int NCH = MM / 64;
    for (int ch = 0; ch < NCH; ch++) {
        if (ch + 1 < NCH) asm volatile("cp.async.wait_group 1;" ::: "memory");
        else              asm volatile("cp.async.wait_group 0;" ::: "memory");
        __syncthreads();
        if (ch + 2 < NCH) pf(ch + 2);

        uint32_t kst = sb + QS_B + (uint32_t)(ch % 3) * STG_B;
        uint32_t vst = kst + 9216u;

        // ---- S = Q K^T : warp tile 16n x 64m (duplicated across c-halves) ----
        float acc_s[8][4] = {};
        #pragma unroll
        for (int jj = 0; jj < 4; jj++) {       // m-pairs (16m each)
            #pragma unroll
            for (int kf = 0; kf < 4; kf++) {
                uint32_t r[4];
                ldsm4(r, kst + (uint32_t)((jj * 16 + lr) * 144 + kf * 32 + lh * 16));
                mma_bf16(acc_s[2 * jj],     q[kf], r);
                mma_bf16(acc_s[2 * jj + 1], q[kf], r + 2);
            }
        }

        // ---- exp -> P fragments in registers + rowsum ----
        uint32_t p[4][4];
        #pragma unroll
        for (int mk = 0; mk < 4; mk++) {
            float e0 = __expf(acc_s[2 * mk][0] - 4.f);
            float e1 = __expf(acc_s[2 * mk][1] - 4.f);
            float e2 = __expf(acc_s[2 * mk][2] - 4.f);
            float e3 = __expf(acc_s[2 * mk][3] - 4.f);
            float f0 = __expf(acc_s[2 * mk + 1][0] - 4.f);
            float f1 = __expf(acc_s[2 * mk + 1][1] - 4.f);
            float f2 = __expf(acc_s[2 * mk + 1][2] - 4.f);
            float f3 = __expf(acc_s[2 * mk + 1][3] - 4.f);
            rs0 += (e0 + e1) + (f0 + f1);
            rs1 += (e2 + e3) + (f2 + f3);
            p[mk][0] = pack_bf16x2(e0, e1);
            p[mk][1] = pack_bf16x2(e2, e3);
            p[mk][2] = pack_bf16x2(f0, f1);
            p[mk][3] = pack_bf16x2(f2, f3);
        }

        // ---- O += P V^T : warp tile 16n x 64c ----
        #pragma unroll
        for (int jj = 0; jj < 4; jj++) {       // c-pairs (16c each)
            #pragma unroll
            for (int mk = 0; mk < 4; mk++) {
                uint32_t r[4];
                ldsm4(r, vst + (uint32_t)((wc + jj * 16 + lr) * 144 + mk * 32 + lh * 16));
                mma_bf16(acc_o[2 * jj],     p[mk], r);
                mma_bf16(acc_o[2 * jj + 1], p[mk], r + 2);
            }
        }
    }

    // ---- rowsum reduce over t (rows warp-private; S duplicated so sums identical) ----
    rs0 += __shfl_xor_sync(0xffffffffu, rs0, 1);
    rs0 += __shfl_xor_sync(0xffffffffu, rs0, 2);
    rs1 += __shfl_xor_sync(0xffffffffu, rs1, 1);
    rs1 += __shfl_xor_sync(0xffffffffu, rs1, 2);
    float inv0 = 1.f / rs0;
    float inv1 = 1.f / rs1;

    // ---- scale + store (16n x 64c per warp) ----
    int n = n0 + wn + g;
    #pragma unroll
    for (int ct = 0; ct < 8; ct++) {
        int c = c0 + wc + ct * 8 + 2 * t;
        size_t base0 = ((size_t)b * 2 * CV + CV + c) * NN;
        size_t base1 = base0 + NN;
        out[base0 + n]     = acc_o[ct][0] * inv0;
        out[base1 + n]     = acc_o[ct][1] * inv0;
        out[base0 + n + 8] = acc_o[ct][2] * inv1;
        out[base1 + n + 8] = acc_o[ct][3] * inv1;
    }
}

// ---------------- copy query_value into out[:, 0:256] ----------------
__global__ void copy_qv_kernel(const float* __restrict__ qv, float* __restrict__ out) {
    int i = blockIdx.x * blockDim.x + threadIdx.x;
    const int per_b = CV * NN / 4;
    if (i >= BB * per_b) return;
    int b = i / per_b;
    int r = i - b * per_b;
    ((float4*)out)[(size_t)b * (2 * CV * NN / 4) + r] = ((const float4*)qv)[i];
}

extern "C" void kernel_launch(void* const* d_in, const int* in_sizes, int n_in,
                              void* d_out, int out_size) {
    const float* memory_keys   = (const float*)d_in[0];
    const float* memory_values = (const float*)d_in[1];
    const float* query_key     = (const float*)d_in[2];
    const float* query_value   = (const float*)d_in[3];
    float* out = (float*)d_out;

    cudaFuncSetAttribute(fused_attn_kernel, cudaFuncAttributeMaxDynamicSharedMemorySize,
                         SMEM_TOTAL);

    prep_kernel<<<10752, 256>>>(memory_keys, memory_values, query_key);

    dim3 gf(CV / 128, NN / 64, BB);   // (2, 64, 2) = 256 CTAs
    fused_attn_kernel<<<gf, 256, SMEM_TOTAL>>>(out);

    copy_qv_kernel<<<(BB * CV * NN / 4) / 256, 256>>>(query_value, out);
}

// round 8
// speedup vs baseline: 1.2844x; 1.2844x over previous
#include <cuda_runtime.h>
#include <cuda_bf16.h>
#include <cstdint>

#define BB 2
#define TT 4
#define CK 64
#define CV 256
#define HH 64
#define WW 64
#define PH 32
#define PW 32
#define MM 4096
#define NN 4096
#define SCALE 0.125f
#define KSPLIT 4
#define MSEG (MM / KSPLIT)   // 1024
#define CHM 32               // m per chunk
#define NCH (MSEG / CHM)     // 32 chunks

// Scratch (device globals: allocation-free)
__device__ __align__(128) __nv_bfloat16 g_qk[(size_t)BB * CK * NN];     // scaled Q, bf16 [b][ck][n]
__device__ __align__(128) __nv_bfloat16 g_mk[(size_t)BB * MM * CK];     // pooled K, bf16 [b][m][ck]
__device__ __align__(128) __nv_bfloat16 g_mv[(size_t)BB * CV * MM];     // pooled V, bf16 [b][c][m]
__device__ __align__(128) float g_opart[(size_t)KSPLIT * BB * CV * NN]; // partial O
__device__ __align__(128) float g_rs[(size_t)KSPLIT * BB * NN];         // partial rowsums

__device__ __forceinline__ void cpasync16(uint32_t saddr, const void* g) {
    asm volatile("cp.async.cg.shared.global [%0], [%1], 16;" :: "r"(saddr), "l"(g));
}
__device__ __forceinline__ void ldsm4(uint32_t* r, uint32_t a) {
    asm volatile("ldmatrix.sync.aligned.m8n8.x4.shared.b16 {%0,%1,%2,%3},[%4];"
                 : "=r"(r[0]), "=r"(r[1]), "=r"(r[2]), "=r"(r[3]) : "r"(a));
}
__device__ __forceinline__ void ldsm4t(uint32_t* r, uint32_t a) {
    asm volatile("ldmatrix.sync.aligned.m8n8.x4.trans.shared.b16 {%0,%1,%2,%3},[%4];"
                 : "=r"(r[0]), "=r"(r[1]), "=r"(r[2]), "=r"(r[3]) : "r"(a));
}
__device__ __forceinline__ void mma_bf16(float* d, const uint32_t* a, const uint32_t* b) {
    asm volatile(
        "mma.sync.aligned.m16n8k16.row.col.f32.bf16.bf16.f32 "
        "{%0,%1,%2,%3},{%4,%5,%6,%7},{%8,%9},{%0,%1,%2,%3};"
        : "+f"(d[0]), "+f"(d[1]), "+f"(d[2]), "+f"(d[3])
        : "r"(a[0]), "r"(a[1]), "r"(a[2]), "r"(a[3]), "r"(b[0]), "r"(b[1]));
}
__device__ __forceinline__ uint32_t pack_bf16x2(float a, float b) {
    __nv_bfloat162 h = __floats2bfloat162_rn(a, b);
    return *reinterpret_cast<uint32_t*>(&h);
}

// ---------------- fused prep: cvtq + pool_keys + pool_vals ----------------
__global__ void __launch_bounds__(256) prep_kernel(const float* __restrict__ mk_in,
                                                   const float* __restrict__ mv_in,
                                                   const float* __restrict__ q_in) {
    int blk = blockIdx.x;
    if (blk < 512) {
        int i = blk * 256 + threadIdx.x;
        float4 v = ((const float4*)q_in)[i];
        __nv_bfloat162* dst = (__nv_bfloat162*)g_qk;
        dst[2 * i]     = __floats2bfloat162_rn(v.x * SCALE, v.y * SCALE);
        dst[2 * i + 1] = __floats2bfloat162_rn(v.z * SCALE, v.w * SCALE);
    } else if (blk < 2560) {
        int idx = (blk - 512) * 256 + threadIdx.x;
        int pw = idx & 31; int t1 = idx >> 5;
        int ph = t1 & 31;  int t2 = t1 >> 5;
        int ck = t2 & 63;  int t3 = t2 >> 6;
        int t  = t3 & 3;   int b  = t3 >> 2;
        const float* base = mk_in + ((((size_t)(b * TT + t) * CK + ck) * HH + ph * 2) * WW + pw * 2);
        float v = fmaxf(fmaxf(base[0], base[1]), fmaxf(base[WW], base[WW + 1]));
        int m = t * (PH * PW) + ph * PW + pw;
        g_mk[((size_t)b * MM + m) * CK + ck] = __float2bfloat16_rn(v);
    } else {
        int idx = (blk - 2560) * 256 + threadIdx.x;
        int pw = idx & 31; int t1 = idx >> 5;
        int ph = t1 & 31;  int t2 = t1 >> 5;
        int c  = t2 & 255; int t3 = t2 >> 8;
        int t  = t3 & 3;   int b  = t3 >> 2;
        const float* base = mv_in + ((((size_t)(b * TT + t) * CV + c) * HH + ph * 2) * WW + pw * 2);
        float v = fmaxf(fmaxf(base[0], base[1]), fmaxf(base[WW], base[WW + 1]));
        int m = t * (PH * PW) + ph * PW + pw;
        g_mv[((size_t)b * CV + c) * MM + m] = __float2bfloat16_rn(v);
    }
}

// ---------------- fused attention with split-K over m ----------------
// CTA: 64n x 128c x 1024m-segment, 4 warps (warp: 16n x 128c, full m-segment).
// grid (8 = 2 c-half * 4 ksplit, 64 n, 2 b) = 1024 CTAs; 3 CTAs/SM.
// smem: Qs[64ck][72n*2B=144B] (9216) | 3 stages: Ks[32m][144B] (4608) + Vs[128c][80B] (10240)
#define QS_B 9216u
#define KST_B 4608u
#define VST_B 10240u
#define STG_B (KST_B + VST_B)            // 14848
#define SMEM_TOTAL (QS_B + 3u * STG_B)   // 53760

__global__ void __launch_bounds__(128, 3) fused_attn_kernel() {
    extern __shared__ char sm[];
    const uint32_t sb = (uint32_t)__cvta_generic_to_shared(sm);
    const int b = blockIdx.z, n0 = blockIdx.y * 64;
    const int c0 = (blockIdx.x & 1) * 128;
    const int ks = blockIdx.x >> 1;
    const int mbase = ks * MSEG;
    const int tid = threadIdx.x;

    const __nv_bfloat16* qb = g_qk + (size_t)b * CK * NN;
    const __nv_bfloat16* kb = g_mk + (size_t)b * MM * CK;
    const __nv_bfloat16* vb = g_mv + (size_t)b * CV * MM;

    // Q load: 64 ck-rows x 8 segs of 16B (pitch 144B)
    #pragma unroll
    for (int i = 0; i < 4; i++) {
        int e = tid + i * 128;
        int row = e >> 3, seg = e & 7;
        cpasync16(sb + (uint32_t)(row * 144 + seg * 16),
                  qb + (size_t)row * NN + n0 + seg * 8);
    }
    asm volatile("cp.async.commit_group;" ::: "memory");

    auto pf = [&](int ch) {
        uint32_t kst = sb + QS_B + (uint32_t)(ch % 3) * STG_B;
        uint32_t vst = kst + KST_B;
        #pragma unroll
        for (int i = 0; i < 2; i++) {          // K: 32 m-rows x 8 segs (pitch 144)
            int e = tid + i * 128;
            int row = e >> 3, seg = e & 7;
            cpasync16(kst + (uint32_t)(row * 144 + seg * 16),
                      kb + (size_t)(mbase + ch * CHM + row) * CK + seg * 8);
        }
        #pragma unroll
        for (int i = 0; i < 4; i++) {          // V: 128 c-rows x 4 segs (pitch 80)
            int e = tid + i * 128;
            int row = e >> 2, seg = e & 3;
            cpasync16(vst + (uint32_t)(row * 80 + seg * 16),
                      vb + (size_t)(c0 + row) * MM + mbase + ch * CHM + seg * 8);
        }
        asm volatile("cp.async.commit_group;" ::: "memory");
    };
    pf(0); pf(1);

    const int wid = tid >> 5, lane = tid & 31;
    const int wn = wid * 16;
    const int g = lane >> 2, t = lane & 3;
    const int lr = (lane & 7) + ((lane >> 4) << 3);
    const int lh = (lane >> 3) & 1;

    asm volatile("cp.async.wait_group 2;" ::: "memory");
    __syncthreads();
    uint32_t q[4][4];
    #pragma unroll
    for (int kf = 0; kf < 4; kf++)
        ldsm4t(q[kf], sb + (uint32_t)((kf * 16 + lr) * 144 + (wn + lh * 8) * 2));

    float acc_o[16][4] = {};
    float rs0 = 0.f, rs1 = 0.f;

    for (int ch = 0; ch < NCH; ch++) {
        if (ch + 1 < NCH) asm volatile("cp.async.wait_group 1;" ::: "memory");
        else              asm volatile("cp.async.wait_group 0;" ::: "memory");
        __syncthreads();
        if (ch + 2 < NCH) pf(ch + 2);

        uint32_t kst = sb + QS_B + (uint32_t)(ch % 3) * STG_B;
        uint32_t vst = kst + KST_B;

        // ---- S = Q K^T : 16n x 32m ----
        float acc_s[4][4] = {};
        #pragma unroll
        for (int jj = 0; jj < 2; jj++) {
            #pragma unroll
            for (int kf = 0; kf < 4; kf++) {
                uint32_t r[4];
                ldsm4(r, kst + (uint32_t)((jj * 16 + lr) * 144 + kf * 32 + lh * 16));
                mma_bf16(acc_s[2 * jj],     q[kf], r);
                mma_bf16(acc_s[2 * jj + 1], q[kf], r + 2);
            }
        }

        // ---- exp -> P fragments + rowsum ----
        uint32_t p[2][4];
        #pragma unroll
        for (int mk = 0; mk < 2; mk++) {
            float e0 = __expf(acc_s[2 * mk][0] - 4.f);
            float e1 = __expf(acc_s[2 * mk][1] - 4.f);
            float e2 = __expf(acc_s[2 * mk][2] - 4.f);
            float e3 = __expf(acc_s[2 * mk][3] - 4.f);
            float f0 = __expf(acc_s[2 * mk + 1][0] - 4.f);
            float f1 = __expf(acc_s[2 * mk + 1][1] - 4.f);
            float f2 = __expf(acc_s[2 * mk + 1][2] - 4.f);
            float f3 = __expf(acc_s[2 * mk + 1][3] - 4.f);
            rs0 += (e0 + e1) + (f0 + f1);
            rs1 += (e2 + e3) + (f2 + f3);
            p[mk][0] = pack_bf16x2(e0, e1);
            p[mk][1] = pack_bf16x2(e2, e3);
            p[mk][2] = pack_bf16x2(f0, f1);
            p[mk][3] = pack_bf16x2(f2, f3);
        }

        // ---- O += P V^T : 16n x 128c ----
        #pragma unroll
        for (int jj = 0; jj < 8; jj++) {
            #pragma unroll
            for (int mk = 0; mk < 2; mk++) {
                uint32_t r[4];
                ldsm4(r, vst + (uint32_t)((jj * 16 + lr) * 80 + mk * 32 + lh * 16));
                mma_bf16(acc_o[2 * jj],     p[mk], r);
                mma_bf16(acc_o[2 * jj + 1], p[mk], r + 2);
            }
        }
    }

    // ---- partial rowsum (reduce over t) ----
    rs0 += __shfl_xor_sync(0xffffffffu, rs0, 1);
    rs0 += __shfl_xor_sync(0xffffffffu, rs0, 2);
    rs1 += __shfl_xor_sync(0xffffffffu, rs1, 1);
    rs1 += __shfl_xor_sync(0xffffffffu, rs1, 2);
    int n = n0 + wn + g;
    if (t == 0) {
        // duplicate write from both c-half CTAs: identical values, benign
        g_rs[((size_t)ks * BB + b) * NN + n]     = rs0;
        g_rs[((size_t)ks * BB + b) * NN + n + 8] = rs1;
    }

    // ---- store unnormalized partial O ----
    float* op = g_opart + ((size_t)ks * BB + b) * CV * NN;
    #pragma unroll
    for (int ct = 0; ct < 16; ct++) {
        int c = c0 + ct * 8 + 2 * t;
        op[(size_t)c * NN + n]           = acc_o[ct][0];
        op[(size_t)(c + 1) * NN + n]     = acc_o[ct][1];
        op[(size_t)c * NN + n + 8]       = acc_o[ct][2];
        op[(size_t)(c + 1) * NN + n + 8] = acc_o[ct][3];
    }
}

// ---------------- combine partials + copy query_value ----------------
// blocks [0, 2048): out[:,CV:2CV] = sum_ks opart * 1/sum_ks rs
// blocks [2048, 4096): out[:,0:CV] = query_value
__global__ void __launch_bounds__(256) combine_kernel(const float* __restrict__ qv,
                                                      float* __restrict__ out) {
    int blk = blockIdx.x;
    if (blk < 2048) {
        int i = blk * 256 + threadIdx.x;        // float4 over [B][CV][NN/4]
        int n4 = i & 1023;                       // NN/4 = 1024
        int bc = i >> 10;                        // b*CV + c
        int b = bc >> 8;
        const float4* rsp = (const float4*)g_rs;
        float4 r = rsp[((size_t)b) * 1024 + n4];                     // ks=0
        float4 r1 = rsp[((size_t)(BB + b)) * 1024 + n4];             // ks=1
        float4 r2 = rsp[((size_t)(2 * BB + b)) * 1024 + n4];
        float4 r3 = rsp[((size_t)(3 * BB + b)) * 1024 + n4];
        float4 inv;
        inv.x = 1.f / (r.x + r1.x + r2.x + r3.x);
        inv.y = 1.f / (r.y + r1.y + r2.y + r3.y);
        inv.z = 1.f / (r.z + r1.z + r2.z + r3.z);
        inv.w = 1.f / (r.w + r1.w + r2.w + r3.w);
        const float4* opp = (const float4*)g_opart;
        float4 o0 = opp[((size_t)0 * BB * CV + bc) * 1024 + n4];
        float4 o1 = opp[((size_t)1 * BB * CV + bc) * 1024 + n4];
        float4 o2 = opp[((size_t)2 * BB * CV + bc) * 1024 + n4];
        float4 o3 = opp[((size_t)3 * BB * CV + bc) * 1024 + n4];
        float4 o;
        o.x = (o0.x + o1.x + o2.x + o3.x) * inv.x;
        o.y = (o0.y + o1.y + o2.y + o3.y) * inv.y;
        o.z = (o0.z + o1.z + o2.z + o3.z) * inv.z;
        o.w = (o0.w + o1.w + o2.w + o3.w) * inv.w;
        ((float4*)out)[((size_t)bc + (size_t)(b + 1) * CV) * 1024 + n4] = o;
    } else {
        int i = (blk - 2048) * 256 + threadIdx.x;
        const int per_b = CV * NN / 4;           // 262144
        int b = i / per_b;
        int r = i - b * per_b;
        ((float4*)out)[(size_t)b * (2 * CV * NN / 4) + r] = ((const float4*)qv)[i];
    }
}

extern "C" void kernel_launch(void* const* d_in, const int* in_sizes, int n_in,
                              void* d_out, int out_size) {
    const float* memory_keys   = (const float*)d_in[0];
    const float* memory_values = (const float*)d_in[1];
    const float* query_key     = (const float*)d_in[2];
    const float* query_value   = (const float*)d_in[3];
    float* out = (float*)d_out;

    cudaFuncSetAttribute(fused_attn_kernel, cudaFuncAttributeMaxDynamicSharedMemorySize,
                         SMEM_TOTAL);

    prep_kernel<<<10752, 256>>>(memory_keys, memory_values, query_key);

    dim3 gf(2 * KSPLIT, NN / 64, BB);   // (8, 64, 2) = 1024 CTAs
    fused_attn_kernel<<<gf, 128, SMEM_TOTAL>>>();

    combine_kernel<<<4096, 256>>>(query_value, out);
}